// round 11
// baseline (speedup 1.0000x reference)
#include <cuda_runtime.h>
#include <cuda_bf16.h>
#include <cstdint>
#include <math.h>

#define HIDDEN 2048
#define NEXP 8
#define GDIM 64
#define BTOK 4096

#define TILE_M 128
#define TILE_N 128
#define BK 64
#define NCHUNKS (HIDDEN / BK)       // 32
#define NSTAGE 3

// bf16 smem tiles
#define A_ROW_B 144
#define B_ROW_B 272
#define A_STAGE_BYTES (128 * A_ROW_B)  // 18432
#define B_STAGE_BYTES (BK * B_ROW_B)   // 17408
#define STAGE_BYTES (A_STAGE_BYTES + B_STAGE_BYTES) // 35840
#define SMEM_HDR 1024
#define SMEM_TOTAL (SMEM_HDR + NSTAGE * STAGE_BYTES) // 108544 -> 2 CTAs/SM

// persistent scheduler
#define TILES_PER_Z 512              // 16 nb x 32 mb
#define TOTAL_TILES ((NEXP + 1) * TILES_PER_Z)  // 4608
#define GEMM_BLOCKS 304              // 152 SMs x 2

// mega-kernel block ranges
#define GBLK 256
#define CXBLK (BTOK * HIDDEN / 4 / 256)
#define CWBLK ((NEXP + 1) * HIDDEN * HIDDEN / 4 / 256)
#define MEGA_BLOCKS (GBLK + CXBLK + CWBLK)

// ---------------- device scratch ----------------
__device__ int   g_cnt[NEXP];
__device__ int   g_tok[NEXP][BTOK];
__device__ float g_wt[NEXP][BTOK];
__device__ float g_psum[NEXP];
__device__ int   g_work;
__device__ uint16_t g_xa[(size_t)BTOK * HIDDEN];
__device__ uint16_t g_wb[(size_t)(NEXP + 1) * HIDDEN * HIDDEN];

// ---------------- helpers ----------------
__device__ __forceinline__ uint32_t smem_u32(const void* p) {
    uint32_t a;
    asm("{ .reg .u64 t; cvta.to.shared.u64 t, %1; cvt.u32.u64 %0, t; }" : "=r"(a) : "l"(p));
    return a;
}
__device__ __forceinline__ void cp16(uint32_t dst, const void* src) {
    asm volatile("cp.async.cg.shared.global [%0], [%1], 16;" :: "r"(dst), "l"(src));
}
#define CP_COMMIT() asm volatile("cp.async.commit_group;" ::: "memory")
#define CP_WAIT(n)  asm volatile("cp.async.wait_group %0;" :: "n"(n) : "memory")

__device__ __forceinline__ void ldsm_x4(uint32_t* r, uint32_t addr) {
    asm volatile("ldmatrix.sync.aligned.m8n8.x4.shared.b16 {%0,%1,%2,%3}, [%4];"
        : "=r"(r[0]), "=r"(r[1]), "=r"(r[2]), "=r"(r[3]) : "r"(addr));
}
__device__ __forceinline__ void ldsm_x4_t(uint32_t* r, uint32_t addr) {
    asm volatile("ldmatrix.sync.aligned.m8n8.x4.trans.shared.b16 {%0,%1,%2,%3}, [%4];"
        : "=r"(r[0]), "=r"(r[1]), "=r"(r[2]), "=r"(r[3]) : "r"(addr));
}
__device__ __forceinline__ void mma_bf16(float* d, const uint32_t* a, uint32_t b0, uint32_t b1) {
    asm volatile(
        "mma.sync.aligned.m16n8k16.row.col.f32.bf16.bf16.f32 "
        "{%0,%1,%2,%3}, {%4,%5,%6,%7}, {%8,%9}, {%0,%1,%2,%3};"
        : "+f"(d[0]), "+f"(d[1]), "+f"(d[2]), "+f"(d[3])
        : "r"(a[0]), "r"(a[1]), "r"(a[2]), "r"(a[3]), "r"(b0), "r"(b1));
}
__device__ __forceinline__ uint32_t pack_bf16(float lo, float hi) {
    uint32_t r;
    asm("cvt.rn.bf16x2.f32 %0, %1, %2;" : "=r"(r) : "f"(hi), "f"(lo));
    return r;
}
__device__ __forceinline__ void red_add_v2(float* p, float a, float b) {
    asm volatile("red.global.add.v2.f32 [%0], {%1, %2};" :: "l"(p), "f"(a), "f"(b) : "memory");
}
__device__ __forceinline__ float sigf(float z) { return 1.f / (1.f + __expf(-z)); }

// ---------------- K0: zero counters ----------------
__global__ void init_kernel() {
    int t = threadIdx.x;
    if (t < NEXP) { g_cnt[t] = 0; g_psum[t] = 0.f; }
    if (t == 0) g_work = 0;
}

// ---------------- K1: mega kernel: gating + convert_x + convert_w ----------------
#define GK 32
__global__ __launch_bounds__(256) void mega_kernel(
    const float* __restrict__ X, const float* __restrict__ noise,
    const float* __restrict__ gw1, const float* __restrict__ gb1,
    const float* __restrict__ gw2, const float* __restrict__ gb2,
    const float* __restrict__ EW, const float* __restrict__ SW,
    const float* __restrict__ p_rs, float* __restrict__ out)
{
    const int bid = blockIdx.x;
    const int tid = threadIdx.x;

    if (bid >= GBLK) {
        if (bid < GBLK + CXBLK) {
            size_t t = (size_t)(bid - GBLK) * 256 + tid;
            float4 v = ((const float4*)X)[t];
            uint2 p;
            p.x = pack_bf16(v.x, v.y);
            p.y = pack_bf16(v.z, v.w);
            ((uint2*)g_xa)[t] = p;
            const float s = 1.f + p_rs[0];
            ((float4*)out)[t] = make_float4(s * v.x, s * v.y, s * v.z, s * v.w);
        } else {
            size_t t = (size_t)(bid - GBLK - CXBLK) * 256 + tid;
            size_t elem = t * 4;
            const size_t EXP_ELEMS = (size_t)NEXP * HIDDEN * HIDDEN;
            float4 v = (elem < EXP_ELEMS) ? ((const float4*)EW)[t]
                                          : *(const float4*)(SW + (elem - EXP_ELEMS));
            uint2 p;
            p.x = pack_bf16(v.x, v.y);
            p.y = pack_bf16(v.z, v.w);
            ((uint2*)g_wb)[t] = p;
        }
        return;
    }

    // ---- gating role: 16 tokens per block, 4-deep cp.async pipeline ----
    __shared__ float xs[4][16][36];
    __shared__ float ws[4][GK][68];
    __shared__ float hs[16][65];
    __shared__ float lg[16][NEXP];
    __shared__ float ws2[GDIM * NEXP];
    __shared__ float bs2[NEXP];

    const int tok0 = bid * 16;
    const int j = tid & 63;
    const int r = tid >> 6;

    const uint32_t xs_b = smem_u32(&xs[0][0][0]);
    const uint32_t ws_b = smem_u32(&ws[0][0][0]);

    ws2[tid]       = gw2[tid];
    ws2[tid + 256] = gw2[tid + 256];
    if (tid < NEXP) bs2[tid] = gb2[tid];

    auto stage = [&](int c, int b) {
        int k0 = c * GK;
        if (tid < 128) {
            int row = tid >> 3, q = tid & 7;
            cp16(xs_b + (uint32_t)(b * 16 * 36 * 4 + row * 36 * 4 + q * 16),
                 &X[(size_t)(tok0 + row) * HIDDEN + k0 + q * 4]);
        }
        #pragma unroll
        for (int jj = 0; jj < 2; jj++) {
            int idx = tid + jj * 256;
            int row = idx >> 4, q = idx & 15;
            cp16(ws_b + (uint32_t)(b * GK * 68 * 4 + row * 68 * 4 + q * 16),
                 &gw1[(size_t)(k0 + row) * GDIM + q * 4]);
        }
        CP_COMMIT();
    };

    float acc[4];
    const float b1 = gb1[j];
    #pragma unroll
    for (int u = 0; u < 4; u++) acc[u] = b1;

    stage(0, 0); stage(1, 1); stage(2, 2);
    for (int c = 0; c < HIDDEN / GK; c++) {
        const int buf = c & 3;
        if (c + 3 < HIDDEN / GK) stage(c + 3, (c + 3) & 3);
        else CP_COMMIT();
        CP_WAIT(3);
        __syncthreads();
        #pragma unroll 8
        for (int kk = 0; kk < GK; kk++) {
            float w = ws[buf][kk][j];
            #pragma unroll
            for (int u = 0; u < 4; u++) acc[u] = fmaf(xs[buf][r + 4 * u][kk], w, acc[u]);
        }
        __syncthreads();
    }
    #pragma unroll
    for (int u = 0; u < 4; u++) hs[r + 4 * u][j] = fmaxf(acc[u], 0.f);
    __syncthreads();

    if (tid < 128) {
        int lt = tid >> 3, e = tid & 7;
        float a = bs2[e];
        #pragma unroll 8
        for (int k = 0; k < GDIM; k++) a = fmaf(hs[lt][k], ws2[k * NEXP + e], a);
        lg[lt][e] = a;
    }
    __syncthreads();

    if (tid < 16) {
        int lt = tid;
        int token = tok0 + lt;
        float g[NEXP];
        float m = -1e30f;
        #pragma unroll
        for (int e = 0; e < NEXP; e++) { g[e] = lg[lt][e]; m = fmaxf(m, g[e]); }
        float s = 0.f;
        #pragma unroll
        for (int e = 0; e < NEXP; e++) { g[e] = expf(g[e] - m); s += g[e]; }
        float inv = 1.f / s;
        #pragma unroll
        for (int e = 0; e < NEXP; e++) {
            g[e] = g[e] * inv + noise[token * NEXP + e] * 0.01f;
            lg[lt][e] = g[e];
        }
        int i1 = 0; float v1 = g[0];
        #pragma unroll
        for (int e = 1; e < NEXP; e++) if (g[e] > v1) { v1 = g[e]; i1 = e; }
        int i2 = -1; float v2 = -1e30f;
        #pragma unroll
        for (int e = 0; e < NEXP; e++) if (e != i1 && g[e] > v2) { v2 = g[e]; i2 = e; }
        float wsum = v1 + v2;
        float w1 = v1 / wsum, w2 = v2 / wsum;
        int p1 = atomicAdd(&g_cnt[i1], 1);
        g_tok[i1][p1] = token; g_wt[i1][p1] = w1;
        int p2 = atomicAdd(&g_cnt[i2], 1);
        g_tok[i2][p2] = token; g_wt[i2][p2] = w2;
    }
    __syncthreads();
    if (tid < NEXP) {
        float s = 0.f;
        #pragma unroll
        for (int t = 0; t < 16; t++) s += lg[t][tid];
        atomicAdd(&g_psum[tid], s);
    }
}

// ---------------- stage loader (bf16 tiles, BK=64) ----------------
template<bool EXPERT>
__device__ __forceinline__ void load_stage(
    const uint16_t* __restrict__ Wb,
    int nb, int mb, const int* __restrict__ toks,
    uint32_t smem_base, int chunk, int buf, int tid)
{
    const uint32_t abase = smem_base + SMEM_HDR + buf * STAGE_BYTES;
    const uint32_t bbase = abase + A_STAGE_BYTES;
    const int k0 = chunk * BK;

    #pragma unroll
    for (int j = 0; j < 4; j++) {
        int idx = tid + j * 256;
        int row = idx >> 3, c = idx & 7;
        int tok = EXPERT ? toks[row] : (mb + row);
        cp16(abase + (uint32_t)(row * A_ROW_B + c * 16),
             g_xa + (size_t)tok * HIDDEN + k0 + c * 8);
    }
    #pragma unroll
    for (int j = 0; j < 4; j++) {
        int idx = tid + j * 256;
        int row = idx >> 4, c = idx & 15;
        cp16(bbase + (uint32_t)(row * B_ROW_B + c * 16),
             Wb + (size_t)(k0 + row) * HIDDEN + nb + c * 8);
    }
    CP_COMMIT();
}

// ---------------- GEMM tile body ----------------
template<bool EXPERT>
__device__ __forceinline__ void gemm_tile(
    const uint16_t* __restrict__ Wb,
    const float* __restrict__ bias, float sc1,
    float* __restrict__ out, int mb, int nb, int cnt, int e)
{
    extern __shared__ char smem[];
    const uint32_t smem_base = smem_u32(smem);
    const int tid = threadIdx.x;
    const int wid = tid >> 5;
    const int lane = tid & 31;
    const int wm = wid & 1;
    const int wn = wid >> 1;

    int*   toks = (int*)smem;
    float* wts  = (float*)(smem + 512);

    if (EXPERT) {
        if (tid < 128) {
            int li = mb + tid;
            toks[tid] = (li < cnt) ? g_tok[e][li] : 0;
            wts[tid]  = (li < cnt) ? g_wt[e][li] : 0.f;
        }
        __syncthreads();
    }

    float acc[4][4][4];
    #pragma unroll
    for (int mt = 0; mt < 4; mt++)
        #pragma unroll
        for (int nt = 0; nt < 4; nt++)
            #pragma unroll
            for (int q = 0; q < 4; q++) acc[mt][nt][q] = 0.f;

    load_stage<EXPERT>(Wb, nb, mb, toks, smem_base, 0, 0, tid);
    load_stage<EXPERT>(Wb, nb, mb, toks, smem_base, 1, 1, tid);

    const uint32_t a_warp = (uint32_t)((lane & 15) * A_ROW_B + (lane >> 4) * 16 + wm * 64 * A_ROW_B);
    const uint32_t b_warp = (uint32_t)((lane & 15) * B_ROW_B + (lane >> 4) * 16 + wn * 64);

    for (int i = 0; i < NCHUNKS; i++) {
        const int buf = i % NSTAGE;
        CP_WAIT(1);
        __syncthreads();

        if (i + 2 < NCHUNKS)
            load_stage<EXPERT>(Wb, nb, mb, toks, smem_base, i + 2, (i + 2) % NSTAGE, tid);
        else
            CP_COMMIT();

        const uint32_t ab = smem_base + SMEM_HDR + buf * STAGE_BYTES + a_warp;
        const uint32_t bb = smem_base + SMEM_HDR + buf * STAGE_BYTES + A_STAGE_BYTES + b_warp;

        #pragma unroll
        for (int ks = 0; ks < 4; ks++) {
            uint32_t af[4][4], bfr[2][4];
            #pragma unroll
            for (int mt = 0; mt < 4; mt++)
                ldsm_x4(af[mt], ab + mt * (16 * A_ROW_B) + ks * 32);
            #pragma unroll
            for (int ng = 0; ng < 2; ng++)
                ldsm_x4_t(bfr[ng], bb + ks * (16 * B_ROW_B) + ng * 32);
            #pragma unroll
            for (int mt = 0; mt < 4; mt++)
                #pragma unroll
                for (int ng = 0; ng < 2; ng++) {
                    mma_bf16(acc[mt][ng * 2 + 0], af[mt], bfr[ng][0], bfr[ng][1]);
                    mma_bf16(acc[mt][ng * 2 + 1], af[mt], bfr[ng][2], bfr[ng][3]);
                }
        }
    }

    const int lq = lane >> 2;
    const int lr = lane & 3;
    #pragma unroll
    for (int mt = 0; mt < 4; mt++) {
        #pragma unroll
        for (int h = 0; h < 2; h++) {
            int mrow = wm * 64 + mt * 16 + lq + h * 8;
            int token;
            float wscale;
            if (EXPERT) {
                if (mb + mrow >= cnt) continue;
                token = toks[mrow];
                wscale = sc1 * wts[mrow];
            } else {
                token = mb + mrow;
                wscale = sc1;
            }
            float* orow = out + (size_t)token * HIDDEN;
            #pragma unroll
            for (int nt = 0; nt < 4; nt++) {
                int col = nb + wn * 32 + nt * 8 + 2 * lr;
                float2 bv = *(const float2*)&bias[col];
                float s0 = wscale * sigf(acc[mt][nt][2 * h]     + bv.x);
                float s1 = wscale * sigf(acc[mt][nt][2 * h + 1] + bv.y);
                red_add_v2(orow + col, s0, s1);
            }
        }
    }
}

// ---------------- K2: persistent fused GEMM (dynamic tile scheduler) ----------------
__global__ __launch_bounds__(256, 2)
void fused_gemm(const float* __restrict__ SBias, const float* __restrict__ p_ss,
                const float* __restrict__ EBias, const float* __restrict__ p_rs,
                float* __restrict__ out, int out_size)
{
    __shared__ int s_v;
    for (;;) {
        __syncthreads();
        if (threadIdx.x == 0) s_v = atomicAdd(&g_work, 1);
        __syncthreads();
        const int v = s_v;
        if (v >= TOTAL_TILES) return;

        const int z   = v >> 9;              // expert / shared
        const int rem = v & 511;
        const int nb  = (rem >> 5) * TILE_N; // nb outer: B strip reused by 32 mb tiles
        const int mb  = (rem & 31) * TILE_M;

        if (z == NEXP) {
            if (rem == 0 && threadIdx.x == 0) {
                float acc = 0.f;
                #pragma unroll
                for (int e = 0; e < NEXP; e++) {
                    float p = g_psum[e] * (1.f / (float)BTOK);
                    float d = 0.125f - p;
                    acc += d * d;
                }
                float loss = acc * (0.01f / 8.f);
                for (long long i = (long long)BTOK * HIDDEN; i < out_size; i++)
                    out[i] = loss;
            }
            gemm_tile<false>(g_wb + (size_t)NEXP * HIDDEN * HIDDEN, SBias, p_ss[0],
                             out, mb, nb, BTOK, 0);
        } else {
            const int cnt = g_cnt[z];
            if (mb >= cnt) continue;
            gemm_tile<true>(g_wb + (size_t)z * HIDDEN * HIDDEN,
                            EBias + (size_t)z * HIDDEN, p_rs[0], out, mb, nb, cnt, z);
        }
    }
}

// ---------------- launcher ----------------
extern "C" void kernel_launch(void* const* d_in, const int* in_sizes, int n_in,
                              void* d_out, int out_size) {
    const float* x      = (const float*)d_in[0];
    const float* noise  = (const float*)d_in[1];
    const float* gw1    = (const float*)d_in[2];
    const float* gb1    = (const float*)d_in[3];
    const float* gw2    = (const float*)d_in[4];
    const float* gb2    = (const float*)d_in[5];
    const float* sw     = (const float*)d_in[6];
    const float* sb     = (const float*)d_in[7];
    const float* sscale = (const float*)d_in[8];
    const float* ew     = (const float*)d_in[9];
    const float* eb     = (const float*)d_in[10];
    const float* rscale = (const float*)d_in[11];
    float* out = (float*)d_out;

    static bool attr_done = false;
    if (!attr_done) {
        cudaFuncSetAttribute(fused_gemm, cudaFuncAttributeMaxDynamicSharedMemorySize, SMEM_TOTAL);
        attr_done = true;
    }

    init_kernel<<<1, 32>>>();
    mega_kernel<<<MEGA_BLOCKS, 256>>>(x, noise, gw1, gb1, gw2, gb2, ew, sw, rscale, out);
    fused_gemm<<<GEMM_BLOCKS, 256, SMEM_TOTAL>>>(sb, sscale, eb, rscale, out, out_size);
}

// round 12
// speedup vs baseline: 1.0821x; 1.0821x over previous
#include <cuda_runtime.h>
#include <cuda_bf16.h>
#include <cstdint>
#include <math.h>

#define HIDDEN 2048
#define NEXP 8
#define GDIM 64
#define BTOK 4096

#define TILE_M 128
#define TILE_N 128
#define BK 64
#define NCHUNKS (HIDDEN / BK)       // 32
#define NSTAGE 3

// bf16 smem tiles
#define A_ROW_B 144
#define B_ROW_B 272
#define A_STAGE_BYTES (128 * A_ROW_B)  // 18432
#define B_STAGE_BYTES (BK * B_ROW_B)   // 17408
#define STAGE_BYTES (A_STAGE_BYTES + B_STAGE_BYTES) // 35840
#define SMEM_HDR 1024
#define SMEM_TOTAL (SMEM_HDR + NSTAGE * STAGE_BYTES) // 108544 -> 2 CTAs/SM

// mega-kernel block ranges (converts do 4 slabs of 256 float4 per block)
#define GBLK 256
#define CXBLK (BTOK * HIDDEN / 4 / 256 / 4)            // 2048
#define CWBLK ((NEXP + 1) * HIDDEN * HIDDEN / 4 / 256 / 4) // 9216
#define MEGA_BLOCKS (GBLK + CXBLK + CWBLK)

// ---------------- device scratch ----------------
__device__ int   g_cnt[NEXP];
__device__ int   g_tok[NEXP][BTOK];
__device__ float g_wt[NEXP][BTOK];
__device__ float g_psum[NEXP];
__device__ uint16_t g_xa[(size_t)BTOK * HIDDEN];
__device__ uint16_t g_wb[(size_t)(NEXP + 1) * HIDDEN * HIDDEN];

// ---------------- helpers ----------------
__device__ __forceinline__ uint32_t smem_u32(const void* p) {
    uint32_t a;
    asm("{ .reg .u64 t; cvta.to.shared.u64 t, %1; cvt.u32.u64 %0, t; }" : "=r"(a) : "l"(p));
    return a;
}
__device__ __forceinline__ void cp16(uint32_t dst, const void* src) {
    asm volatile("cp.async.cg.shared.global [%0], [%1], 16;" :: "r"(dst), "l"(src));
}
#define CP_COMMIT() asm volatile("cp.async.commit_group;" ::: "memory")
#define CP_WAIT(n)  asm volatile("cp.async.wait_group %0;" :: "n"(n) : "memory")

__device__ __forceinline__ void ldsm_x4(uint32_t* r, uint32_t addr) {
    asm volatile("ldmatrix.sync.aligned.m8n8.x4.shared.b16 {%0,%1,%2,%3}, [%4];"
        : "=r"(r[0]), "=r"(r[1]), "=r"(r[2]), "=r"(r[3]) : "r"(addr));
}
__device__ __forceinline__ void ldsm_x4_t(uint32_t* r, uint32_t addr) {
    asm volatile("ldmatrix.sync.aligned.m8n8.x4.trans.shared.b16 {%0,%1,%2,%3}, [%4];"
        : "=r"(r[0]), "=r"(r[1]), "=r"(r[2]), "=r"(r[3]) : "r"(addr));
}
__device__ __forceinline__ void mma_bf16(float* d, const uint32_t* a, uint32_t b0, uint32_t b1) {
    asm volatile(
        "mma.sync.aligned.m16n8k16.row.col.f32.bf16.bf16.f32 "
        "{%0,%1,%2,%3}, {%4,%5,%6,%7}, {%8,%9}, {%0,%1,%2,%3};"
        : "+f"(d[0]), "+f"(d[1]), "+f"(d[2]), "+f"(d[3])
        : "r"(a[0]), "r"(a[1]), "r"(a[2]), "r"(a[3]), "r"(b0), "r"(b1));
}
__device__ __forceinline__ uint32_t pack_bf16(float lo, float hi) {
    uint32_t r;
    asm("cvt.rn.bf16x2.f32 %0, %1, %2;" : "=r"(r) : "f"(hi), "f"(lo));
    return r;
}
__device__ __forceinline__ void red_add_v2(float* p, float a, float b) {
    asm volatile("red.global.add.v2.f32 [%0], {%1, %2};" :: "l"(p), "f"(a), "f"(b) : "memory");
}
__device__ __forceinline__ float sigf(float z) { return 1.f / (1.f + __expf(-z)); }

// ---------------- K0: zero counters ----------------
__global__ void init_kernel() {
    int t = threadIdx.x;
    if (t < NEXP) { g_cnt[t] = 0; g_psum[t] = 0.f; }
}

// ---------------- K1: mega kernel: gating + convert_x + convert_w ----------------
#define GK 32
__global__ __launch_bounds__(256) void mega_kernel(
    const float* __restrict__ X, const float* __restrict__ noise,
    const float* __restrict__ gw1, const float* __restrict__ gb1,
    const float* __restrict__ gw2, const float* __restrict__ gb2,
    const float* __restrict__ EW, const float* __restrict__ SW,
    const float* __restrict__ p_rs, float* __restrict__ out)
{
    const int bid = blockIdx.x;
    const int tid = threadIdx.x;

    if (bid >= GBLK) {
        if (bid < GBLK + CXBLK) {
            // X convert + out base init: 4 slabs, MLP=4
            size_t base = (size_t)(bid - GBLK) * 1024 + tid;
            float4 v[4];
            #pragma unroll
            for (int j = 0; j < 4; j++) v[j] = ((const float4*)X)[base + j * 256];
            const float s = 1.f + p_rs[0];
            #pragma unroll
            for (int j = 0; j < 4; j++) {
                uint2 p;
                p.x = pack_bf16(v[j].x, v[j].y);
                p.y = pack_bf16(v[j].z, v[j].w);
                ((uint2*)g_xa)[base + j * 256] = p;
                ((float4*)out)[base + j * 256] =
                    make_float4(s * v[j].x, s * v[j].y, s * v[j].z, s * v[j].w);
            }
        } else {
            // W convert: 4 slabs, MLP=4
            size_t base = (size_t)(bid - GBLK - CXBLK) * 1024 + tid;
            const size_t EXP_Q = (size_t)NEXP * HIDDEN * HIDDEN / 4;  // float4 count in EW
            float4 v[4];
            #pragma unroll
            for (int j = 0; j < 4; j++) {
                size_t t = base + j * 256;
                v[j] = (t < EXP_Q) ? ((const float4*)EW)[t]
                                   : ((const float4*)SW)[t - EXP_Q];
            }
            #pragma unroll
            for (int j = 0; j < 4; j++) {
                uint2 p;
                p.x = pack_bf16(v[j].x, v[j].y);
                p.y = pack_bf16(v[j].z, v[j].w);
                ((uint2*)g_wb)[base + j * 256] = p;
            }
        }
        return;
    }

    // ---- gating role: 16 tokens per block, 4-deep cp.async pipeline ----
    __shared__ float xs[4][16][36];
    __shared__ float ws[4][GK][68];
    __shared__ float hs[16][65];
    __shared__ float lg[16][NEXP];
    __shared__ float ws2[GDIM * NEXP];
    __shared__ float bs2[NEXP];

    const int tok0 = bid * 16;
    const int j = tid & 63;
    const int r = tid >> 6;

    const uint32_t xs_b = smem_u32(&xs[0][0][0]);
    const uint32_t ws_b = smem_u32(&ws[0][0][0]);

    ws2[tid]       = gw2[tid];
    ws2[tid + 256] = gw2[tid + 256];
    if (tid < NEXP) bs2[tid] = gb2[tid];

    auto stage = [&](int c, int b) {
        int k0 = c * GK;
        if (tid < 128) {
            int row = tid >> 3, q = tid & 7;
            cp16(xs_b + (uint32_t)(b * 16 * 36 * 4 + row * 36 * 4 + q * 16),
                 &X[(size_t)(tok0 + row) * HIDDEN + k0 + q * 4]);
        }
        #pragma unroll
        for (int jj = 0; jj < 2; jj++) {
            int idx = tid + jj * 256;
            int row = idx >> 4, q = idx & 15;
            cp16(ws_b + (uint32_t)(b * GK * 68 * 4 + row * 68 * 4 + q * 16),
                 &gw1[(size_t)(k0 + row) * GDIM + q * 4]);
        }
        CP_COMMIT();
    };

    float acc[4];
    const float b1 = gb1[j];
    #pragma unroll
    for (int u = 0; u < 4; u++) acc[u] = b1;

    stage(0, 0); stage(1, 1); stage(2, 2);
    for (int c = 0; c < HIDDEN / GK; c++) {
        const int buf = c & 3;
        if (c + 3 < HIDDEN / GK) stage(c + 3, (c + 3) & 3);
        else CP_COMMIT();
        CP_WAIT(3);
        __syncthreads();
        #pragma unroll 8
        for (int kk = 0; kk < GK; kk++) {
            float w = ws[buf][kk][j];
            #pragma unroll
            for (int u = 0; u < 4; u++) acc[u] = fmaf(xs[buf][r + 4 * u][kk], w, acc[u]);
        }
        __syncthreads();
    }
    #pragma unroll
    for (int u = 0; u < 4; u++) hs[r + 4 * u][j] = fmaxf(acc[u], 0.f);
    __syncthreads();

    if (tid < 128) {
        int lt = tid >> 3, e = tid & 7;
        float a = bs2[e];
        #pragma unroll 8
        for (int k = 0; k < GDIM; k++) a = fmaf(hs[lt][k], ws2[k * NEXP + e], a);
        lg[lt][e] = a;
    }
    __syncthreads();

    if (tid < 16) {
        int lt = tid;
        int token = tok0 + lt;
        float g[NEXP];
        float m = -1e30f;
        #pragma unroll
        for (int e = 0; e < NEXP; e++) { g[e] = lg[lt][e]; m = fmaxf(m, g[e]); }
        float s = 0.f;
        #pragma unroll
        for (int e = 0; e < NEXP; e++) { g[e] = expf(g[e] - m); s += g[e]; }
        float inv = 1.f / s;
        #pragma unroll
        for (int e = 0; e < NEXP; e++) {
            g[e] = g[e] * inv + noise[token * NEXP + e] * 0.01f;
            lg[lt][e] = g[e];
        }
        int i1 = 0; float v1 = g[0];
        #pragma unroll
        for (int e = 1; e < NEXP; e++) if (g[e] > v1) { v1 = g[e]; i1 = e; }
        int i2 = -1; float v2 = -1e30f;
        #pragma unroll
        for (int e = 0; e < NEXP; e++) if (e != i1 && g[e] > v2) { v2 = g[e]; i2 = e; }
        float wsum = v1 + v2;
        float w1 = v1 / wsum, w2 = v2 / wsum;
        int p1 = atomicAdd(&g_cnt[i1], 1);
        g_tok[i1][p1] = token; g_wt[i1][p1] = w1;
        int p2 = atomicAdd(&g_cnt[i2], 1);
        g_tok[i2][p2] = token; g_wt[i2][p2] = w2;
    }
    __syncthreads();
    if (tid < NEXP) {
        float s = 0.f;
        #pragma unroll
        for (int t = 0; t < 16; t++) s += lg[t][tid];
        atomicAdd(&g_psum[tid], s);
    }
}

// ---------------- stage loader (bf16 tiles, BK=64) ----------------
template<bool EXPERT>
__device__ __forceinline__ void load_stage(
    const uint16_t* __restrict__ Wb,
    int nb, int mb, const int* __restrict__ toks,
    uint32_t smem_base, int chunk, int buf, int tid)
{
    const uint32_t abase = smem_base + SMEM_HDR + buf * STAGE_BYTES;
    const uint32_t bbase = abase + A_STAGE_BYTES;
    const int k0 = chunk * BK;

    #pragma unroll
    for (int j = 0; j < 4; j++) {
        int idx = tid + j * 256;
        int row = idx >> 3, c = idx & 7;
        int tok = EXPERT ? toks[row] : (mb + row);
        cp16(abase + (uint32_t)(row * A_ROW_B + c * 16),
             g_xa + (size_t)tok * HIDDEN + k0 + c * 8);
    }
    #pragma unroll
    for (int j = 0; j < 4; j++) {
        int idx = tid + j * 256;
        int row = idx >> 4, c = idx & 15;
        cp16(bbase + (uint32_t)(row * B_ROW_B + c * 16),
             Wb + (size_t)(k0 + row) * HIDDEN + nb + c * 8);
    }
    CP_COMMIT();
}

// ---------------- GEMM tile body ----------------
template<bool EXPERT>
__device__ __forceinline__ void gemm_tile(
    const uint16_t* __restrict__ Wb,
    const float* __restrict__ bias, float sc1,
    float* __restrict__ out, int mb, int nb, int cnt, int e)
{
    extern __shared__ char smem[];
    const uint32_t smem_base = smem_u32(smem);
    const int tid = threadIdx.x;
    const int wid = tid >> 5;
    const int lane = tid & 31;
    const int wm = wid & 1;
    const int wn = wid >> 1;

    int*   toks = (int*)smem;
    float* wts  = (float*)(smem + 512);

    if (EXPERT) {
        if (tid < 128) {
            int li = mb + tid;
            toks[tid] = (li < cnt) ? g_tok[e][li] : 0;
            wts[tid]  = (li < cnt) ? g_wt[e][li] : 0.f;
        }
        __syncthreads();
    }

    float acc[4][4][4];
    #pragma unroll
    for (int mt = 0; mt < 4; mt++)
        #pragma unroll
        for (int nt = 0; nt < 4; nt++)
            #pragma unroll
            for (int q = 0; q < 4; q++) acc[mt][nt][q] = 0.f;

    load_stage<EXPERT>(Wb, nb, mb, toks, smem_base, 0, 0, tid);
    load_stage<EXPERT>(Wb, nb, mb, toks, smem_base, 1, 1, tid);

    const uint32_t a_warp = (uint32_t)((lane & 15) * A_ROW_B + (lane >> 4) * 16 + wm * 64 * A_ROW_B);
    const uint32_t b_warp = (uint32_t)((lane & 15) * B_ROW_B + (lane >> 4) * 16 + wn * 64);

    for (int i = 0; i < NCHUNKS; i++) {
        const int buf = i % NSTAGE;
        CP_WAIT(1);
        __syncthreads();

        if (i + 2 < NCHUNKS)
            load_stage<EXPERT>(Wb, nb, mb, toks, smem_base, i + 2, (i + 2) % NSTAGE, tid);
        else
            CP_COMMIT();

        const uint32_t ab = smem_base + SMEM_HDR + buf * STAGE_BYTES + a_warp;
        const uint32_t bb = smem_base + SMEM_HDR + buf * STAGE_BYTES + A_STAGE_BYTES + b_warp;

        #pragma unroll
        for (int ks = 0; ks < 4; ks++) {
            uint32_t af[4][4], bfr[2][4];
            #pragma unroll
            for (int mt = 0; mt < 4; mt++)
                ldsm_x4(af[mt], ab + mt * (16 * A_ROW_B) + ks * 32);
            #pragma unroll
            for (int ng = 0; ng < 2; ng++)
                ldsm_x4_t(bfr[ng], bb + ks * (16 * B_ROW_B) + ng * 32);
            #pragma unroll
            for (int mt = 0; mt < 4; mt++)
                #pragma unroll
                for (int ng = 0; ng < 2; ng++) {
                    mma_bf16(acc[mt][ng * 2 + 0], af[mt], bfr[ng][0], bfr[ng][1]);
                    mma_bf16(acc[mt][ng * 2 + 1], af[mt], bfr[ng][2], bfr[ng][3]);
                }
        }
    }

    const int lq = lane >> 2;
    const int lr = lane & 3;
    #pragma unroll
    for (int mt = 0; mt < 4; mt++) {
        #pragma unroll
        for (int h = 0; h < 2; h++) {
            int mrow = wm * 64 + mt * 16 + lq + h * 8;
            int token;
            float wscale;
            if (EXPERT) {
                if (mb + mrow >= cnt) continue;
                token = toks[mrow];
                wscale = sc1 * wts[mrow];
            } else {
                token = mb + mrow;
                wscale = sc1;
            }
            float* orow = out + (size_t)token * HIDDEN;
            #pragma unroll
            for (int nt = 0; nt < 4; nt++) {
                int col = nb + wn * 32 + nt * 8 + 2 * lr;
                float2 bv = *(const float2*)&bias[col];
                float s0 = wscale * sigf(acc[mt][nt][2 * h]     + bv.x);
                float s1 = wscale * sigf(acc[mt][nt][2 * h + 1] + bv.y);
                red_add_v2(orow + col, s0, s1);
            }
        }
    }
}

// ---------------- K2: fused shared + expert GEMM (+ gate loss) ----------------
__global__ __launch_bounds__(256, 2)
void fused_gemm(const float* __restrict__ SBias, const float* __restrict__ p_ss,
                const float* __restrict__ EBias, const float* __restrict__ p_rs,
                float* __restrict__ out, int out_size)
{
    const int nb = blockIdx.y * TILE_N;
    const int mb = blockIdx.x * TILE_M;
    if (blockIdx.z == NEXP) {
        if (mb == 0 && nb == 0 && threadIdx.x == 0) {
            float acc = 0.f;
            #pragma unroll
            for (int e = 0; e < NEXP; e++) {
                float p = g_psum[e] * (1.f / (float)BTOK);
                float d = 0.125f - p;
                acc += d * d;
            }
            float loss = acc * (0.01f / 8.f);
            for (long long i = (long long)BTOK * HIDDEN; i < out_size; i++)
                out[i] = loss;
        }
        gemm_tile<false>(g_wb + (size_t)NEXP * HIDDEN * HIDDEN, SBias, p_ss[0],
                         out, mb, nb, BTOK, 0);
    } else {
        const int e = blockIdx.z;
        const int cnt = g_cnt[e];
        if (mb >= cnt) return;
        gemm_tile<true>(g_wb + (size_t)e * HIDDEN * HIDDEN,
                        EBias + (size_t)e * HIDDEN, p_rs[0], out, mb, nb, cnt, e);
    }
}

// ---------------- launcher ----------------
extern "C" void kernel_launch(void* const* d_in, const int* in_sizes, int n_in,
                              void* d_out, int out_size) {
    const float* x      = (const float*)d_in[0];
    const float* noise  = (const float*)d_in[1];
    const float* gw1    = (const float*)d_in[2];
    const float* gb1    = (const float*)d_in[3];
    const float* gw2    = (const float*)d_in[4];
    const float* gb2    = (const float*)d_in[5];
    const float* sw     = (const float*)d_in[6];
    const float* sb     = (const float*)d_in[7];
    const float* sscale = (const float*)d_in[8];
    const float* ew     = (const float*)d_in[9];
    const float* eb     = (const float*)d_in[10];
    const float* rscale = (const float*)d_in[11];
    float* out = (float*)d_out;

    static bool attr_done = false;
    if (!attr_done) {
        cudaFuncSetAttribute(fused_gemm, cudaFuncAttributeMaxDynamicSharedMemorySize, SMEM_TOTAL);
        attr_done = true;
    }

    init_kernel<<<1, 32>>>();
    mega_kernel<<<MEGA_BLOCKS, 256>>>(x, noise, gw1, gb1, gw2, gb2, ew, sw, rscale, out);
    fused_gemm<<<dim3(BTOK / TILE_M, HIDDEN / TILE_N, NEXP + 1), 256, SMEM_TOTAL>>>(
        sb, sscale, eb, rscale, out, out_size);
}